// round 8
// baseline (speedup 1.0000x reference)
#include <cuda_runtime.h>
#include <cstdint>
#include <math_constants.h>

// ---------------- problem constants ----------------
#define CCH 512
#define HF 50
#define WF 75
#define HWP (HF * WF)          // 3750
#define NROI 512
#define FCIN 25088
#define FCD 4096
#define GN 4096
#define NLOC 84
#define NSC 21
#define NHEAD 105

#if defined(__CUDA_ARCH__) && defined(__CUDA_ARCH_FEAT_SM103_ALL)
#define HAS_TCGEN05 1
#else
#define HAS_TCGEN05 0
#endif

// ---------------- device scratch ----------------
__device__ float g_xt[(size_t)HWP * CCH];        // 7.7 MB x transposed [h*w][c]
__device__ float g_pool[(size_t)NROI * FCIN];    // 51.4 MB, k' = bin*512 + c order
__device__ float g_fc1[(size_t)NROI * FCD];      // 8 MB (tf32-rounded)
__device__ float g_fc2[(size_t)NROI * FCD];      // 8 MB
__device__ float g_wt[(size_t)NHEAD * FCD];      // head weights transposed

// ---------------- common helpers ----------------
__device__ __forceinline__ float tf32_rn(float x) {
    float r;
    asm("cvt.rna.tf32.f32 %0, %1;" : "=f"(r) : "f"(x));
    return r;
}
__device__ __forceinline__ uint32_t smem_u32(const void* p) {
    uint32_t a;
    asm("{ .reg .u64 t; cvta.to.shared.u64 t, %1; cvt.u32.u64 %0, t; }" : "=r"(a) : "l"(p));
    return a;
}
__device__ __forceinline__ void cpasync16(uint32_t dst, const void* src) {
    asm volatile("cp.async.cg.shared.global [%0], [%1], 16;" :: "r"(dst), "l"(src));
}
#define SWZ(x) ((x) ^ (((x) >> 3) & 0x70))

#if HAS_TCGEN05
__device__ __forceinline__ void mbar_init(uint32_t mbar, uint32_t cnt) {
    asm volatile("mbarrier.init.shared.b64 [%0], %1;" :: "r"(mbar), "r"(cnt) : "memory");
}
__device__ __forceinline__ void mbar_wait(uint32_t mbar, uint32_t parity) {
    asm volatile(
        "{\n\t.reg .pred P;\n"
        "LW_%=:\n\t"
        "mbarrier.try_wait.parity.acquire.cta.shared::cta.b64 P, [%0], %1, 0x989680;\n\t"
        "@P bra.uni LD_%=;\n\t"
        "bra.uni LW_%=;\n"
        "LD_%=:\n\t}"
        :: "r"(mbar), "r"(parity) : "memory");
}
__device__ __forceinline__ void mbar_arrive(uint32_t mbar) {
    asm volatile("mbarrier.arrive.shared.b64 _, [%0];" :: "r"(mbar) : "memory");
}
__device__ __forceinline__ void cpasync_arrive(uint32_t mbar) {
    asm volatile("cp.async.mbarrier.arrive.noinc.shared.b64 [%0];" :: "r"(mbar) : "memory");
}
__device__ __forceinline__ void tmem_alloc(uint32_t smem_dst, uint32_t ncols) {
    asm volatile("tcgen05.alloc.cta_group::1.sync.aligned.shared::cta.b32 [%0], %1;"
                 :: "r"(smem_dst), "r"(ncols) : "memory");
}
__device__ __forceinline__ void tmem_dealloc(uint32_t tmem, uint32_t ncols) {
    asm volatile("tcgen05.dealloc.cta_group::1.sync.aligned.b32 %0, %1;" :: "r"(tmem), "r"(ncols));
}
__device__ __forceinline__ void tmem_relinquish() {
    asm volatile("tcgen05.relinquish_alloc_permit.cta_group::1.sync.aligned;");
}
__device__ __forceinline__ void tcommit(uint32_t mbar) {
    asm volatile("tcgen05.commit.cta_group::1.mbarrier::arrive::one.shared::cluster.b64 [%0];"
                 :: "r"(mbar) : "memory");
}
__device__ __forceinline__ void tc_fence_after() {
    asm volatile("tcgen05.fence::after_thread_sync;" ::: "memory");
}
__device__ __forceinline__ void fence_async_smem() {
    asm volatile("fence.proxy.async.shared::cta;" ::: "memory");
}
__device__ __forceinline__ void mma_tf32(uint32_t d, uint64_t ad, uint64_t bd,
                                         uint32_t idesc, uint32_t accum) {
    asm volatile(
        "{\n\t.reg .pred p;\n\t"
        "setp.ne.u32 p, %4, 0;\n\t"
        "tcgen05.mma.cta_group::1.kind::tf32 [%0], %1, %2, %3, {%5, %5, %5, %5}, p;\n\t}"
        :: "r"(d), "l"(ad), "l"(bd), "r"(idesc), "r"(accum), "r"(0u) : "memory");
}
__device__ __forceinline__ void ldtm_x32(uint32_t* r, uint32_t ta) {
    asm volatile(
        "tcgen05.ld.sync.aligned.32x32b.x32.b32 "
        "{%0,%1,%2,%3,%4,%5,%6,%7,%8,%9,%10,%11,%12,%13,%14,%15,"
        "%16,%17,%18,%19,%20,%21,%22,%23,%24,%25,%26,%27,%28,%29,%30,%31}, [%32];"
        : "=r"(r[0]), "=r"(r[1]), "=r"(r[2]), "=r"(r[3]), "=r"(r[4]), "=r"(r[5]), "=r"(r[6]), "=r"(r[7]),
          "=r"(r[8]), "=r"(r[9]), "=r"(r[10]), "=r"(r[11]), "=r"(r[12]), "=r"(r[13]), "=r"(r[14]), "=r"(r[15]),
          "=r"(r[16]), "=r"(r[17]), "=r"(r[18]), "=r"(r[19]), "=r"(r[20]), "=r"(r[21]), "=r"(r[22]), "=r"(r[23]),
          "=r"(r[24]), "=r"(r[25]), "=r"(r[26]), "=r"(r[27]), "=r"(r[28]), "=r"(r[29]), "=r"(r[30]), "=r"(r[31])
        : "r"(ta));
}
#define LDTM_WAIT() asm volatile("tcgen05.wait::ld.sync.aligned;" ::: "memory")

// K-major SW128 descriptor: LBO=1, SBO=64, version=1
static constexpr uint64_t DESC_K =
    (2ULL << 61) | (1ULL << 46) | (64ULL << 32) | (1ULL << 16);
// idesc: F32 acc, tf32 a/b, K-major both, M=128, N=128
static constexpr uint32_t IDESC_TF32_N128 = 0x8200910u;
#endif  // HAS_TCGEN05

#define NSTAGE 5
#define SM_TOTAL 166912

// ---------------- x transpose: x[c][p] -> xT[p][c] ----------------
__global__ __launch_bounds__(256)
void xt_kernel(const float* __restrict__ x, float* __restrict__ xT)
{
    __shared__ float t[32][33];
    int pb = blockIdx.x * 32, cb = blockIdx.y * 32;
    int tx = threadIdx.x & 31, ty = threadIdx.x >> 5;
    #pragma unroll
    for (int i = 0; i < 32; i += 8) {
        int p = pb + tx;
        if (p < HWP) t[ty + i][tx] = x[(size_t)(cb + ty + i) * HWP + p];
    }
    __syncthreads();
    #pragma unroll
    for (int i = 0; i < 32; i += 8) {
        int p = pb + ty + i;
        if (p < HWP) xT[(size_t)p * CCH + cb + tx] = t[tx][ty + i];
    }
}

// ---------------- RoI adaptive max pool (channel-coalesced) ----------------
// block = roi, 512 threads = channels. Output k' = (ph*7+pw)*512 + c.
__global__ __launch_bounds__(512)
void roi_pool_kernel(const float* __restrict__ xT,
                     const float* __restrict__ rois,
                     float* __restrict__ pool)
{
    int n = blockIdx.x;
    int c = threadIdx.x;
    __shared__ int rs[7], re[7], cs[7], ce[7];
    if (c == 0) {
        int x1 = (int)(rois[n * 4 + 0] * 0.0625f);
        int y1 = (int)(rois[n * 4 + 1] * 0.0625f);
        int x2 = (int)(rois[n * 4 + 2] * 0.0625f);
        int y2 = (int)(rois[n * 4 + 3] * 0.0625f);
        int h = y2 - y1 + 1;
        int w = x2 - x1 + 1;
        #pragma unroll
        for (int p = 0; p < 7; p++) {
            rs[p] = y1 + (p * h) / 7;
            re[p] = y1 + ((p + 1) * h + 6) / 7;
            cs[p] = x1 + (p * w) / 7;
            ce[p] = x1 + ((p + 1) * w + 6) / 7;
        }
    }
    __syncthreads();

    float* out = pool + (size_t)n * FCIN + c;
    #pragma unroll
    for (int ph = 0; ph < 7; ph++) {
        #pragma unroll
        for (int pw = 0; pw < 7; pw++) {
            float m = -CUDART_INF_F;
            for (int y = rs[ph]; y < re[ph]; y++) {
                const float* row = xT + ((size_t)y * WF) * CCH + c;
                for (int xx = cs[pw]; xx < ce[pw]; xx++)
                    m = fmaxf(m, row[(size_t)xx * CCH]);
            }
            out[(ph * 7 + pw) * 512] = tf32_rn(m);
        }
    }
}

// row index of W for flattened-k index k' (GEMM1 permuted order)
__device__ __forceinline__ int krow_perm(int kp) {
    return (kp & 511) * 49 + (kp >> 9);   // k' = bin*512+c -> k = c*49+bin
}

// ---------------- warp-specialized tcgen05 tf32 GEMM, fused B transpose ----------------
// C[512,GN] = relu(A[512,K] @ W[K,GN] + bias). W read directly in [K,N] layout;
// producers (warps 0-7) LDG W rows, tf32-round, STS into K-major swizzled tiles.
// warp 8 lane 0: MMA issuer. Epilogue: warps 0-7.
template <bool RELU, bool ROUND_OUT, bool PERMUTE>
__global__ __launch_bounds__(288, 1)
void gemm_kernel(int K,
                 const float* __restrict__ A,
                 const float* __restrict__ W,
                 const float* __restrict__ bias,
                 float* __restrict__ C)
{
    extern __shared__ char smem[];
    const int tid = threadIdx.x;
    const int m0 = blockIdx.y * 128;
    const int n0 = blockIdx.x * 128;

#if HAS_TCGEN05
    const uint32_t sbase = smem_u32(smem);
    const uint32_t ubase = (sbase + 128 + 1023) & ~1023u;
    char* uptr = smem + (ubase - sbase);
    const int wid = tid >> 5, lid = tid & 31;
    const int nt = K >> 5;
    const uint32_t mb_full  = sbase + 16;
    const uint32_t mb_empty = sbase + 56;
    const uint32_t mb_done  = sbase + 96;

    if (tid == 0) {
        #pragma unroll
        for (int s = 0; s < NSTAGE; s++) {
            mbar_init(mb_full + s * 8, 512);   // 256 cp.async + 256 STS arrivals
            mbar_init(mb_empty + s * 8, 1);
        }
        mbar_init(mb_done, 1);
    }
    if (wid == 0) {
        tmem_alloc(sbase, 128);
        tmem_relinquish();
    }
    __syncthreads();
    const uint32_t tmem = *(const volatile uint32_t*)smem;

    const float* Abase = A + (size_t)m0 * K;

    if (wid < 8) {
        // -------- producers: A via cp.async, B via LDG+round+STS-transpose --------
        const int r  = tid & 31;     // k-row within tile
        const int ng = tid >> 5;     // n-group (8 groups x 16 floats)
        for (int t = 0; t < nt; t++) {
            int s = t - (t / NSTAGE) * NSTAGE;
            if (t >= NSTAGE)
                mbar_wait(mb_empty + s * 8, (t / NSTAGE - 1) & 1);
            uint32_t dA = ubase + s * 32768;
            const float* Ab = Abase + (size_t)t * 32;
            #pragma unroll
            for (int i = 0; i < 4; i++) {
                int idx = tid + i * 256;
                int row = idx >> 3, cc = idx & 7;
                cpasync16(dA + SWZ(row * 128 + cc * 16), Ab + (size_t)row * K + cc * 4);
            }
            cpasync_arrive(mb_full + s * 8);

            // B: source row of W for this tile/lane
            int kr = PERMUTE ? (((t & 15) * 32 + r) * 49 + (t >> 4))
                             : (t * 32 + r);
            const float4* src = (const float4*)(W + (size_t)kr * GN + n0 + ng * 16);
            float4 v0 = src[0], v1 = src[1], v2 = src[2], v3 = src[3];
            float vv[16] = {v0.x, v0.y, v0.z, v0.w, v1.x, v1.y, v1.z, v1.w,
                            v2.x, v2.y, v2.z, v2.w, v3.x, v3.y, v3.z, v3.w};
            char* bstage = uptr + s * 32768 + 16384;
            #pragma unroll
            for (int j = 0; j < 16; j++) {
                int nl = ng * 16 + j;
                *(float*)(bstage + SWZ(nl * 128 + r * 4)) = tf32_rn(vv[j]);
            }
            mbar_arrive(mb_full + s * 8);
        }
    } else if (tid == 256) {
        // -------- MMA issuer --------
        for (int t = 0; t < nt; t++) {
            int s = t - (t / NSTAGE) * NSTAGE;
            mbar_wait(mb_full + s * 8, (t / NSTAGE) & 1);
            fence_async_smem();
            tc_fence_after();
            uint32_t aaddr = ubase + s * 32768;
            uint32_t baddr = aaddr + 16384;
            uint64_t ad = DESC_K | ((aaddr >> 4) & 0x3FFF);
            uint64_t bd = DESC_K | ((baddr >> 4) & 0x3FFF);
            #pragma unroll
            for (int ks = 0; ks < 4; ks++)
                mma_tf32(tmem, ad + ks * 2, bd + ks * 2,
                         IDESC_TF32_N128, (t > 0 || ks > 0) ? 1u : 0u);
            tcommit(mb_empty + s * 8);
        }
        tcommit(mb_done);
    }

    // -------- epilogue: warps 0-7, each reads its subpartition, half the cols --------
    mbar_wait(mb_done, 0);
    __syncthreads();
    tc_fence_after();
    if (wid < 8) {
        int sub = wid & 3, half = wid >> 2;
        int m = m0 + sub * 32 + lid;
        #pragma unroll
        for (int i = 0; i < 2; i++) {
            int cb = half * 2 + i;
            uint32_t rr[32];
            ldtm_x32(rr, tmem + cb * 32);
            LDTM_WAIT();
            float* Crow = C + (size_t)m * GN + n0 + cb * 32;
            const float* brow = bias + n0 + cb * 32;
            #pragma unroll
            for (int j = 0; j < 32; j++) {
                float v = __uint_as_float(rr[j]) + brow[j];
                if (RELU) v = fmaxf(v, 0.f);
                if (ROUND_OUT) v = tf32_rn(v);
                Crow[j] = v;
            }
        }
    }
    __syncthreads();
    if (wid == 0) tmem_dealloc(tmem, 128);

#else  // ---------------- fp32 fallback (contingency; W in [K,N]) ----------------
    float* As = (float*)smem;                 // [16][132]
    float* Bs = (float*)smem + 16 * 132;      // [16][128]
    const int tx = tid & 15;
    const int ty = tid >> 4;                  // valid for tid<256

    float acc[8][8];
    #pragma unroll
    for (int i = 0; i < 8; i++)
        #pragma unroll
        for (int j = 0; j < 8; j++) acc[i][j] = 0.f;

    const float* Ablk = A + (size_t)m0 * K;

    for (int k0 = 0; k0 < K; k0 += 16) {
        if (tid < 256) {
            #pragma unroll
            for (int t = 0; t < 2; t++) {
                int idx = tid + t * 256;
                int row = idx >> 2;
                int kc  = (idx & 3) * 4;
                float4 v = *(const float4*)(Ablk + (size_t)row * K + k0 + kc);
                As[(kc + 0) * 132 + row] = v.x;
                As[(kc + 1) * 132 + row] = v.y;
                As[(kc + 2) * 132 + row] = v.z;
                As[(kc + 3) * 132 + row] = v.w;
            }
            #pragma unroll
            for (int t = 0; t < 2; t++) {
                int idx = tid + t * 256;
                int row = idx >> 5;
                int n4  = (idx & 31) * 4;
                int kp = k0 + row;
                int kr = PERMUTE ? krow_perm(kp) : kp;
                *(float4*)&Bs[row * 128 + n4] =
                    *(const float4*)(W + (size_t)kr * GN + n0 + n4);
            }
        }
        __syncthreads();
        if (tid < 256) {
            #pragma unroll
            for (int k = 0; k < 16; k++) {
                float a[8], b[8];
                *(float4*)&a[0] = *(const float4*)&As[k * 132 + ty * 8 + 0];
                *(float4*)&a[4] = *(const float4*)&As[k * 132 + ty * 8 + 4];
                *(float4*)&b[0] = *(const float4*)&Bs[k * 128 + tx * 8 + 0];
                *(float4*)&b[4] = *(const float4*)&Bs[k * 128 + tx * 8 + 4];
                #pragma unroll
                for (int i = 0; i < 8; i++)
                    #pragma unroll
                    for (int j = 0; j < 8; j++)
                        acc[i][j] = fmaf(a[i], b[j], acc[i][j]);
            }
        }
        __syncthreads();
    }

    if (tid < 256) {
        #pragma unroll
        for (int i = 0; i < 8; i++) {
            int m = m0 + ty * 8 + i;
            #pragma unroll
            for (int j = 0; j < 8; j++) {
                int n = n0 + tx * 8 + j;
                float v = acc[i][j] + bias[n];
                if (RELU) v = fmaxf(v, 0.f);
                if (ROUND_OUT) v = tf32_rn(v);
                C[(size_t)m * GN + n] = v;
            }
        }
    }
#endif
}

// ---------------- head weight transpose ----------------
__global__ void transpose_head_kernel(const float* __restrict__ Wl,
                                      const float* __restrict__ Ws,
                                      float* __restrict__ Wt)
{
    int idx = blockIdx.x * 256 + threadIdx.x;
    if (idx >= NHEAD * FCD) return;
    int o = idx >> 12, k = idx & 4095;
    Wt[idx] = (o < NLOC) ? Wl[(size_t)k * NLOC + o] : Ws[(size_t)k * NSC + (o - NLOC)];
}

// ---------------- head: 8 rois/block, warp-per-output ----------------
__global__ __launch_bounds__(256, 1)
void head_kernel(const float* __restrict__ fc,
                 const float* __restrict__ Wt,
                 const float* __restrict__ bl, const float* __restrict__ bs,
                 float* __restrict__ out_loc, float* __restrict__ out_sc)
{
    extern __shared__ float sfc[];   // 8 x 4096
    int b0 = blockIdx.x * 8;
    int tid = threadIdx.x;
    for (int r = 0; r < 8; r++)
        for (int k = tid; k < FCD; k += 256)
            sfc[r * FCD + k] = fc[(size_t)(b0 + r) * FCD + k];
    __syncthreads();

    int w = tid >> 5, lane = tid & 31;
    for (int o = w; o < NHEAD; o += 8) {
        const float4* wp = (const float4*)(Wt + (size_t)o * FCD);
        float acc[8];
        #pragma unroll
        for (int r = 0; r < 8; r++) acc[r] = 0.f;
        for (int k4 = lane; k4 < FCD / 4; k4 += 32) {
            float4 wv = wp[k4];
            #pragma unroll
            for (int r = 0; r < 8; r++) {
                float4 f = *(const float4*)&sfc[r * FCD + k4 * 4];
                acc[r] += wv.x * f.x + wv.y * f.y + wv.z * f.z + wv.w * f.w;
            }
        }
        #pragma unroll
        for (int off = 16; off; off >>= 1)
            #pragma unroll
            for (int r = 0; r < 8; r++)
                acc[r] += __shfl_xor_sync(0xFFFFFFFFu, acc[r], off);
        if (lane == 0) {
            if (o < NLOC) {
                float b = bl[o];
                #pragma unroll
                for (int r = 0; r < 8; r++) out_loc[(size_t)(b0 + r) * NLOC + o] = acc[r] + b;
            } else {
                float b = bs[o - NLOC];
                #pragma unroll
                for (int r = 0; r < 8; r++) out_sc[(size_t)(b0 + r) * NSC + (o - NLOC)] = acc[r] + b;
            }
        }
    }
}

// ---------------- launch ----------------
extern "C" void kernel_launch(void* const* d_in, const int* in_sizes, int n_in,
                              void* d_out, int out_size)
{
    const float* x      = (const float*)d_in[0];
    const float* rois   = (const float*)d_in[1];
    const float* W1     = (const float*)d_in[2];
    const float* b1     = (const float*)d_in[3];
    const float* W2     = (const float*)d_in[4];
    const float* b2     = (const float*)d_in[5];
    const float* W_loc  = (const float*)d_in[6];
    const float* b_loc  = (const float*)d_in[7];
    const float* W_sc   = (const float*)d_in[8];
    const float* b_sc   = (const float*)d_in[9];
    float* out = (float*)d_out;

    float *p_xt, *p_pool, *p_fc1, *p_fc2, *p_wt;
    cudaGetSymbolAddress((void**)&p_xt,   g_xt);
    cudaGetSymbolAddress((void**)&p_pool, g_pool);
    cudaGetSymbolAddress((void**)&p_fc1,  g_fc1);
    cudaGetSymbolAddress((void**)&p_fc2,  g_fc2);
    cudaGetSymbolAddress((void**)&p_wt,   g_wt);

    cudaFuncSetAttribute(gemm_kernel<true, true, true>,
                         cudaFuncAttributeMaxDynamicSharedMemorySize, SM_TOTAL);
    cudaFuncSetAttribute(gemm_kernel<true, false, false>,
                         cudaFuncAttributeMaxDynamicSharedMemorySize, SM_TOTAL);
    cudaFuncSetAttribute(head_kernel,
                         cudaFuncAttributeMaxDynamicSharedMemorySize, 8 * FCD * 4);

    // 0) transpose x -> xT[p][c]
    {
        dim3 gx((HWP + 31) / 32, CCH / 32);
        xt_kernel<<<gx, 256>>>(x, p_xt);
    }

    // 1) RoI adaptive max pool (coalesced, bin-major layout)
    roi_pool_kernel<<<NROI, 512>>>(p_xt, rois, p_pool);

    // 2) fc1 = relu(pool @ W1 + b1)  (producers permute W1 rows, round to tf32)
    dim3 g(GN / 128, NROI / 128);
    gemm_kernel<true, true, true><<<g, 288, SM_TOTAL>>>(FCIN, p_pool, W1, b1, p_fc1);

    // 3) fc2 = relu(fc1 @ W2 + b2)
    gemm_kernel<true, false, false><<<g, 288, SM_TOTAL>>>(FCD, p_fc1, W2, b2, p_fc2);

    // 4) head
    transpose_head_kernel<<<(NHEAD * FCD) / 256, 256>>>(W_loc, W_sc, p_wt);
    head_kernel<<<NROI / 8, 256, 8 * FCD * 4>>>(p_fc2, p_wt, b_loc, b_sc,
                                                out, out + (size_t)NROI * NLOC);
}

// round 11
// speedup vs baseline: 1.6405x; 1.6405x over previous
#include <cuda_runtime.h>
#include <cstdint>
#include <math_constants.h>

// ---------------- problem constants ----------------
#define CCH 512
#define HF 50
#define WF 75
#define HWP (HF * WF)          // 3750
#define NROI 512
#define FCIN 25088
#define FCD 4096
#define GN 4096
#define NLOC 84
#define NSC 21
#define NHEAD 105

#if defined(__CUDA_ARCH__) && defined(__CUDA_ARCH_FEAT_SM103_ALL)
#define HAS_TCGEN05 1
#else
#define HAS_TCGEN05 0
#endif

// ---------------- device scratch ----------------
__device__ float g_xt[(size_t)HWP * CCH];        // 7.7 MB x transposed [h*w][c]
__device__ float g_pool[(size_t)NROI * FCIN];    // 51.4 MB, k' = bin*512 + c order
__device__ float g_fc1[(size_t)NROI * FCD];      // 8 MB (tf32-rounded)
__device__ float g_fc2[(size_t)NROI * FCD];      // 8 MB
__device__ float g_w1t[(size_t)FCIN * FCD];      // 411 MB W1^T [N, k'] tf32
__device__ float g_w2t[(size_t)FCD * FCD];       // 67 MB  W2^T [N, k] tf32
__device__ float g_wt[(size_t)NHEAD * FCD];      // head weights transposed

// ---------------- common helpers ----------------
__device__ __forceinline__ float tf32_rn(float x) {
    float r;
    asm("cvt.rna.tf32.f32 %0, %1;" : "=f"(r) : "f"(x));
    return r;
}
__device__ __forceinline__ uint32_t smem_u32(const void* p) {
    uint32_t a;
    asm("{ .reg .u64 t; cvta.to.shared.u64 t, %1; cvt.u32.u64 %0, t; }" : "=r"(a) : "l"(p));
    return a;
}
__device__ __forceinline__ void cpasync16(uint32_t dst, const void* src) {
    asm volatile("cp.async.cg.shared.global [%0], [%1], 16;" :: "r"(dst), "l"(src));
}
#define SWZ(x) ((x) ^ (((x) >> 3) & 0x70))

#if HAS_TCGEN05
__device__ __forceinline__ void mbar_init(uint32_t mbar, uint32_t cnt) {
    asm volatile("mbarrier.init.shared.b64 [%0], %1;" :: "r"(mbar), "r"(cnt) : "memory");
}
__device__ __forceinline__ void mbar_wait(uint32_t mbar, uint32_t parity) {
    asm volatile(
        "{\n\t.reg .pred P;\n"
        "LW_%=:\n\t"
        "mbarrier.try_wait.parity.acquire.cta.shared::cta.b64 P, [%0], %1, 0x989680;\n\t"
        "@P bra.uni LD_%=;\n\t"
        "bra.uni LW_%=;\n"
        "LD_%=:\n\t}"
        :: "r"(mbar), "r"(parity) : "memory");
}
__device__ __forceinline__ void cpasync_arrive(uint32_t mbar) {
    asm volatile("cp.async.mbarrier.arrive.noinc.shared.b64 [%0];" :: "r"(mbar) : "memory");
}
__device__ __forceinline__ void tmem_alloc(uint32_t smem_dst, uint32_t ncols) {
    asm volatile("tcgen05.alloc.cta_group::1.sync.aligned.shared::cta.b32 [%0], %1;"
                 :: "r"(smem_dst), "r"(ncols) : "memory");
}
__device__ __forceinline__ void tmem_dealloc(uint32_t tmem, uint32_t ncols) {
    asm volatile("tcgen05.dealloc.cta_group::1.sync.aligned.b32 %0, %1;" :: "r"(tmem), "r"(ncols));
}
__device__ __forceinline__ void tmem_relinquish() {
    asm volatile("tcgen05.relinquish_alloc_permit.cta_group::1.sync.aligned;");
}
__device__ __forceinline__ void tcommit(uint32_t mbar) {
    asm volatile("tcgen05.commit.cta_group::1.mbarrier::arrive::one.shared::cluster.b64 [%0];"
                 :: "r"(mbar) : "memory");
}
__device__ __forceinline__ void tc_fence_after() {
    asm volatile("tcgen05.fence::after_thread_sync;" ::: "memory");
}
__device__ __forceinline__ void fence_async_smem() {
    asm volatile("fence.proxy.async.shared::cta;" ::: "memory");
}
__device__ __forceinline__ void mma_tf32(uint32_t d, uint64_t ad, uint64_t bd,
                                         uint32_t idesc, uint32_t accum) {
    asm volatile(
        "{\n\t.reg .pred p;\n\t"
        "setp.ne.u32 p, %4, 0;\n\t"
        "tcgen05.mma.cta_group::1.kind::tf32 [%0], %1, %2, %3, {%5, %5, %5, %5}, p;\n\t}"
        :: "r"(d), "l"(ad), "l"(bd), "r"(idesc), "r"(accum), "r"(0u) : "memory");
}
__device__ __forceinline__ void ldtm_x32(uint32_t* r, uint32_t ta) {
    asm volatile(
        "tcgen05.ld.sync.aligned.32x32b.x32.b32 "
        "{%0,%1,%2,%3,%4,%5,%6,%7,%8,%9,%10,%11,%12,%13,%14,%15,"
        "%16,%17,%18,%19,%20,%21,%22,%23,%24,%25,%26,%27,%28,%29,%30,%31}, [%32];"
        : "=r"(r[0]), "=r"(r[1]), "=r"(r[2]), "=r"(r[3]), "=r"(r[4]), "=r"(r[5]), "=r"(r[6]), "=r"(r[7]),
          "=r"(r[8]), "=r"(r[9]), "=r"(r[10]), "=r"(r[11]), "=r"(r[12]), "=r"(r[13]), "=r"(r[14]), "=r"(r[15]),
          "=r"(r[16]), "=r"(r[17]), "=r"(r[18]), "=r"(r[19]), "=r"(r[20]), "=r"(r[21]), "=r"(r[22]), "=r"(r[23]),
          "=r"(r[24]), "=r"(r[25]), "=r"(r[26]), "=r"(r[27]), "=r"(r[28]), "=r"(r[29]), "=r"(r[30]), "=r"(r[31])
        : "r"(ta));
}
#define LDTM_WAIT() asm volatile("tcgen05.wait::ld.sync.aligned;" ::: "memory")

// K-major SW128 descriptor: LBO=1, SBO=64, version=1
static constexpr uint64_t DESC_K =
    (2ULL << 61) | (1ULL << 46) | (64ULL << 32) | (1ULL << 16);
// idesc: F32 acc, tf32 a/b, K-major both, M=128, N=128
static constexpr uint32_t IDESC_TF32_N128 = 0x8200910u;
#endif  // HAS_TCGEN05

#define NSTAGE 5
#define SM_TOTAL 166912

// ---------------- x transpose: x[c][p] -> xT[p][c] ----------------
__global__ __launch_bounds__(256)
void xt_kernel(const float* __restrict__ x, float* __restrict__ xT)
{
    __shared__ float t[32][33];
    int pb = blockIdx.x * 32, cb = blockIdx.y * 32;
    int tx = threadIdx.x & 31, ty = threadIdx.x >> 5;
    #pragma unroll
    for (int i = 0; i < 32; i += 8) {
        int p = pb + tx;
        if (p < HWP) t[ty + i][tx] = x[(size_t)(cb + ty + i) * HWP + p];
    }
    __syncthreads();
    #pragma unroll
    for (int i = 0; i < 32; i += 8) {
        int p = pb + ty + i;
        if (p < HWP) xT[(size_t)p * CCH + cb + tx] = t[tx][ty + i];
    }
}

// ---------------- RoI adaptive max pool (channel-coalesced) ----------------
// block = roi, 512 threads = channels. Output k' = (ph*7+pw)*512 + c.
__global__ __launch_bounds__(512)
void roi_pool_kernel(const float* __restrict__ xT,
                     const float* __restrict__ rois,
                     float* __restrict__ pool)
{
    int n = blockIdx.x;
    int c = threadIdx.x;
    __shared__ int rs[7], re[7], cs[7], ce[7];
    if (c == 0) {
        int x1 = (int)(rois[n * 4 + 0] * 0.0625f);
        int y1 = (int)(rois[n * 4 + 1] * 0.0625f);
        int x2 = (int)(rois[n * 4 + 2] * 0.0625f);
        int y2 = (int)(rois[n * 4 + 3] * 0.0625f);
        int h = y2 - y1 + 1;
        int w = x2 - x1 + 1;
        #pragma unroll
        for (int p = 0; p < 7; p++) {
            rs[p] = y1 + (p * h) / 7;
            re[p] = y1 + ((p + 1) * h + 6) / 7;
            cs[p] = x1 + (p * w) / 7;
            ce[p] = x1 + ((p + 1) * w + 6) / 7;
        }
    }
    __syncthreads();

    float* out = pool + (size_t)n * FCIN + c;
    #pragma unroll
    for (int ph = 0; ph < 7; ph++) {
        #pragma unroll
        for (int pw = 0; pw < 7; pw++) {
            float m = -CUDART_INF_F;
            for (int y = rs[ph]; y < re[ph]; y++) {
                const float* row = xT + ((size_t)y * WF) * CCH + c;
                for (int xx = cs[pw]; xx < ce[pw]; xx++)
                    m = fmaxf(m, row[(size_t)xx * CCH]);
            }
            out[(ph * 7 + pw) * 512] = tf32_rn(m);
        }
    }
}

// ---------------- transpose + round (optional k-permute): Wt[n][kp] = rn(W[perm(kp)][n]) ----------------
// PERM: kp = bin*512 + c  ->  source row k = c*49 + bin (absorbs pool's bin-major layout).
template <bool PERM>
__global__ __launch_bounds__(256)
void transpose_round_kernel(const float* __restrict__ W, float* __restrict__ Wt,
                            int K, int N)
{
    __shared__ float t[32][33];
    int kb = blockIdx.y * 32, nb = blockIdx.x * 32;
    int tx = threadIdx.x & 31, ty = threadIdx.x >> 5;
    #pragma unroll
    for (int i = 0; i < 32; i += 8) {
        int kp = kb + ty + i;
        int k = PERM ? ((kp & 511) * 49 + (kp >> 9)) : kp;
        t[ty + i][tx] = tf32_rn(W[(size_t)k * N + nb + tx]);
    }
    __syncthreads();
    #pragma unroll
    for (int i = 0; i < 32; i += 8)
        Wt[(size_t)(nb + ty + i) * K + kb + tx] = t[tx][ty + i];
}

// ---------------- warp-specialized tcgen05 tf32 GEMM (R5 design) ----------------
// C[512,GN] = relu(A[512,K] @ Bt[GN,K]^T + bias). A,Bt row-major, K-major tiles.
// warps 0-3: cp.async producers; tid 128: MMA issuer; warps 4-7: epilogue.
template <bool RELU, bool ROUND_OUT>
__global__ __launch_bounds__(256, 1)
void gemm_kernel(int K,
                 const float* __restrict__ A,
                 const float* __restrict__ Bt,
                 const float* __restrict__ bias,
                 float* __restrict__ C)
{
    extern __shared__ char smem[];
    const int tid = threadIdx.x;
    const int m0 = blockIdx.y * 128;
    const int n0 = blockIdx.x * 128;

#if HAS_TCGEN05
    const uint32_t sbase = smem_u32(smem);
    const uint32_t ubase = (sbase + 128 + 1023) & ~1023u;
    const int wid = tid >> 5, lid = tid & 31;
    const int nt = K >> 5;
    const uint32_t mb_full  = sbase + 16;
    const uint32_t mb_empty = sbase + 56;
    const uint32_t mb_done  = sbase + 96;

    if (tid == 0) {
        #pragma unroll
        for (int s = 0; s < NSTAGE; s++) {
            mbar_init(mb_full + s * 8, 128);   // 128 producer threads
            mbar_init(mb_empty + s * 8, 1);
        }
        mbar_init(mb_done, 1);
    }
    if (wid == 0) {
        tmem_alloc(sbase, 128);
        tmem_relinquish();
    }
    __syncthreads();
    const uint32_t tmem = *(const volatile uint32_t*)smem;

    const float* Abase = A  + (size_t)m0 * K;
    const float* Bbase = Bt + (size_t)n0 * K;

    if (wid < 4) {
        // ---------------- producers ----------------
        for (int t = 0; t < nt; t++) {
            int s = t - (t / NSTAGE) * NSTAGE;
            if (t >= NSTAGE)
                mbar_wait(mb_empty + s * 8, (t / NSTAGE - 1) & 1);
            uint32_t dA = ubase + s * 32768;
            uint32_t dB = dA + 16384;
            const float* Ab = Abase + (size_t)t * 32;
            const float* Bb = Bbase + (size_t)t * 32;
            #pragma unroll
            for (int i = 0; i < 8; i++) {
                int idx = tid + i * 128;
                int row = idx >> 3, c = idx & 7;
                cpasync16(dA + SWZ(row * 128 + c * 16), Ab + (size_t)row * K + c * 4);
            }
            #pragma unroll
            for (int i = 0; i < 8; i++) {
                int idx = tid + i * 128;
                int row = idx >> 3, c = idx & 7;
                cpasync16(dB + SWZ(row * 128 + c * 16), Bb + (size_t)row * K + c * 4);
            }
            cpasync_arrive(mb_full + s * 8);
        }
    } else if (tid == 128) {
        // ---------------- MMA issuer ----------------
        for (int t = 0; t < nt; t++) {
            int s = t - (t / NSTAGE) * NSTAGE;
            mbar_wait(mb_full + s * 8, (t / NSTAGE) & 1);
            fence_async_smem();
            tc_fence_after();
            uint32_t aaddr = ubase + s * 32768;
            uint32_t baddr = aaddr + 16384;
            uint64_t ad = DESC_K | ((aaddr >> 4) & 0x3FFF);
            uint64_t bd = DESC_K | ((baddr >> 4) & 0x3FFF);
            #pragma unroll
            for (int ks = 0; ks < 4; ks++)     // 4 K-steps of 8 (32B each)
                mma_tf32(tmem, ad + ks * 2, bd + ks * 2,
                         IDESC_TF32_N128, (t > 0 || ks > 0) ? 1u : 0u);
            tcommit(mb_empty + s * 8);
        }
        tcommit(mb_done);
    }

    // ---------------- epilogue ----------------
    mbar_wait(mb_done, 0);
    __syncthreads();
    tc_fence_after();
    if (wid >= 4) {
        int m = m0 + (wid & 3) * 32 + lid;
        #pragma unroll
        for (int cb = 0; cb < 4; cb++) {
            uint32_t r[32];
            ldtm_x32(r, tmem + cb * 32);
            LDTM_WAIT();
            float* Crow = C + (size_t)m * GN + n0 + cb * 32;
            const float* brow = bias + n0 + cb * 32;
            #pragma unroll
            for (int i = 0; i < 32; i++) {
                float v = __uint_as_float(r[i]) + brow[i];
                if (RELU) v = fmaxf(v, 0.f);
                if (ROUND_OUT) v = tf32_rn(v);
                Crow[i] = v;
            }
        }
    }
    __syncthreads();
    if (wid == 0) tmem_dealloc(tmem, 128);

#else  // ---------------- fp32 fallback (non-103a pass; Bt[n][k]) ----------------
    float* As = (float*)smem;                 // [16][132]
    float* Bs = (float*)smem + 16 * 132;      // [128][18]
    const int tx = tid & 15;
    const int ty = tid >> 4;

    float acc[8][8];
    #pragma unroll
    for (int i = 0; i < 8; i++)
        #pragma unroll
        for (int j = 0; j < 8; j++) acc[i][j] = 0.f;

    const float* Ablk = A  + (size_t)m0 * K;
    const float* Bblk = Bt + (size_t)n0 * K;

    for (int k0 = 0; k0 < K; k0 += 16) {
        #pragma unroll
        for (int t = 0; t < 2; t++) {
            int idx = tid + t * 256;
            int row = idx >> 2;
            int kc  = (idx & 3) * 4;
            float4 v = *(const float4*)(Ablk + (size_t)row * K + k0 + kc);
            As[(kc + 0) * 132 + row] = v.x;
            As[(kc + 1) * 132 + row] = v.y;
            As[(kc + 2) * 132 + row] = v.z;
            As[(kc + 3) * 132 + row] = v.w;
        }
        #pragma unroll
        for (int t = 0; t < 2; t++) {
            int idx = tid + t * 256;
            int row = idx >> 2;
            int kc  = (idx & 3) * 4;
            float4 v = *(const float4*)(Bblk + (size_t)row * K + k0 + kc);
            Bs[row * 18 + kc + 0] = v.x;
            Bs[row * 18 + kc + 1] = v.y;
            Bs[row * 18 + kc + 2] = v.z;
            Bs[row * 18 + kc + 3] = v.w;
        }
        __syncthreads();

        #pragma unroll
        for (int k = 0; k < 16; k++) {
            float a[8], b[8];
            *(float4*)&a[0] = *(const float4*)&As[k * 132 + ty * 8 + 0];
            *(float4*)&a[4] = *(const float4*)&As[k * 132 + ty * 8 + 4];
            #pragma unroll
            for (int j = 0; j < 8; j++) b[j] = Bs[(tx * 8 + j) * 18 + k];
            #pragma unroll
            for (int i = 0; i < 8; i++)
                #pragma unroll
                for (int j = 0; j < 8; j++)
                    acc[i][j] = fmaf(a[i], b[j], acc[i][j]);
        }
        __syncthreads();
    }

    #pragma unroll
    for (int i = 0; i < 8; i++) {
        int m = m0 + ty * 8 + i;
        #pragma unroll
        for (int j = 0; j < 8; j++) {
            int n = n0 + tx * 8 + j;
            float v = acc[i][j] + bias[n];
            if (RELU) v = fmaxf(v, 0.f);
            if (ROUND_OUT) v = tf32_rn(v);
            C[(size_t)m * GN + n] = v;
        }
    }
#endif
}

// ---------------- head weight transpose ----------------
__global__ void transpose_head_kernel(const float* __restrict__ Wl,
                                      const float* __restrict__ Ws,
                                      float* __restrict__ Wt)
{
    int idx = blockIdx.x * 256 + threadIdx.x;
    if (idx >= NHEAD * FCD) return;
    int o = idx >> 12, k = idx & 4095;
    Wt[idx] = (o < NLOC) ? Wl[(size_t)k * NLOC + o] : Ws[(size_t)k * NSC + (o - NLOC)];
}

// ---------------- head: 8 rois/block, warp-per-output ----------------
__global__ __launch_bounds__(256, 1)
void head_kernel(const float* __restrict__ fc,
                 const float* __restrict__ Wt,
                 const float* __restrict__ bl, const float* __restrict__ bs,
                 float* __restrict__ out_loc, float* __restrict__ out_sc)
{
    extern __shared__ float sfc[];   // 8 x 4096
    int b0 = blockIdx.x * 8;
    int tid = threadIdx.x;
    for (int r = 0; r < 8; r++)
        for (int k = tid; k < FCD; k += 256)
            sfc[r * FCD + k] = fc[(size_t)(b0 + r) * FCD + k];
    __syncthreads();

    int w = tid >> 5, lane = tid & 31;
    for (int o = w; o < NHEAD; o += 8) {
        const float4* wp = (const float4*)(Wt + (size_t)o * FCD);
        float acc[8];
        #pragma unroll
        for (int r = 0; r < 8; r++) acc[r] = 0.f;
        for (int k4 = lane; k4 < FCD / 4; k4 += 32) {
            float4 wv = wp[k4];
            #pragma unroll
            for (int r = 0; r < 8; r++) {
                float4 f = *(const float4*)&sfc[r * FCD + k4 * 4];
                acc[r] += wv.x * f.x + wv.y * f.y + wv.z * f.z + wv.w * f.w;
            }
        }
        #pragma unroll
        for (int off = 16; off; off >>= 1)
            #pragma unroll
            for (int r = 0; r < 8; r++)
                acc[r] += __shfl_xor_sync(0xFFFFFFFFu, acc[r], off);
        if (lane == 0) {
            if (o < NLOC) {
                float b = bl[o];
                #pragma unroll
                for (int r = 0; r < 8; r++) out_loc[(size_t)(b0 + r) * NLOC + o] = acc[r] + b;
            } else {
                float b = bs[o - NLOC];
                #pragma unroll
                for (int r = 0; r < 8; r++) out_sc[(size_t)(b0 + r) * NSC + (o - NLOC)] = acc[r] + b;
            }
        }
    }
}

// ---------------- launch ----------------
extern "C" void kernel_launch(void* const* d_in, const int* in_sizes, int n_in,
                              void* d_out, int out_size)
{
    const float* x      = (const float*)d_in[0];
    const float* rois   = (const float*)d_in[1];
    const float* W1     = (const float*)d_in[2];
    const float* b1     = (const float*)d_in[3];
    const float* W2     = (const float*)d_in[4];
    const float* b2     = (const float*)d_in[5];
    const float* W_loc  = (const float*)d_in[6];
    const float* b_loc  = (const float*)d_in[7];
    const float* W_sc   = (const float*)d_in[8];
    const float* b_sc   = (const float*)d_in[9];
    float* out = (float*)d_out;

    float *p_xt, *p_pool, *p_fc1, *p_fc2, *p_wt, *p_w1t, *p_w2t;
    cudaGetSymbolAddress((void**)&p_xt,   g_xt);
    cudaGetSymbolAddress((void**)&p_pool, g_pool);
    cudaGetSymbolAddress((void**)&p_fc1,  g_fc1);
    cudaGetSymbolAddress((void**)&p_fc2,  g_fc2);
    cudaGetSymbolAddress((void**)&p_wt,   g_wt);
    cudaGetSymbolAddress((void**)&p_w1t,  g_w1t);
    cudaGetSymbolAddress((void**)&p_w2t,  g_w2t);

    cudaFuncSetAttribute(gemm_kernel<true, true>,
                         cudaFuncAttributeMaxDynamicSharedMemorySize, SM_TOTAL);
    cudaFuncSetAttribute(gemm_kernel<true, false>,
                         cudaFuncAttributeMaxDynamicSharedMemorySize, SM_TOTAL);
    cudaFuncSetAttribute(head_kernel,
                         cudaFuncAttributeMaxDynamicSharedMemorySize, 8 * FCD * 4);

    // 0) x -> xT[p][c]; weights -> Wt[n][k] (tf32, W1 with k-permutation)
    {
        dim3 gx((HWP + 31) / 32, CCH / 32);
        xt_kernel<<<gx, 256>>>(x, p_xt);
        dim3 gt1(FCD / 32, FCIN / 32);
        transpose_round_kernel<true><<<gt1, 256>>>(W1, p_w1t, FCIN, FCD);
        dim3 gt2(FCD / 32, FCD / 32);
        transpose_round_kernel<false><<<gt2, 256>>>(W2, p_w2t, FCD, FCD);
    }

    // 1) RoI adaptive max pool (coalesced, bin-major k')
    roi_pool_kernel<<<NROI, 512>>>(p_xt, rois, p_pool);

    // 2) fc1 = relu(pool @ W1 + b1)
    dim3 g(GN / 128, NROI / 128);
    gemm_kernel<true, true><<<g, 256, SM_TOTAL>>>(FCIN, p_pool, p_w1t, b1, p_fc1);

    // 3) fc2 = relu(fc1 @ W2 + b2)
    gemm_kernel<true, false><<<g, 256, SM_TOTAL>>>(FCD, p_fc1, p_w2t, b2, p_fc2);

    // 4) head
    transpose_head_kernel<<<(NHEAD * FCD) / 256, 256>>>(W_loc, W_sc, p_wt);
    head_kernel<<<NROI / 8, 256, 8 * FCD * 4>>>(p_fc2, p_wt, b_loc, b_sc,
                                                out, out + (size_t)NROI * NLOC);
}

// round 12
// speedup vs baseline: 1.9416x; 1.1835x over previous
#include <cuda_runtime.h>
#include <cstdint>
#include <math_constants.h>

// ---------------- problem constants ----------------
#define CCH 512
#define HF 50
#define WF 75
#define HWP (HF * WF)          // 3750
#define NROI 512
#define FCIN 25088
#define FCD 4096
#define GN 4096
#define NLOC 84
#define NSC 21
#define NHEAD 105

#if defined(__CUDA_ARCH__) && defined(__CUDA_ARCH_FEAT_SM103_ALL)
#define HAS_TCGEN05 1
#else
#define HAS_TCGEN05 0
#endif

// ---------------- device scratch ----------------
__device__ float g_xt[(size_t)HWP * CCH];        // 7.7 MB x transposed [h*w][c]
__device__ float g_pool[(size_t)NROI * FCIN];    // 51.4 MB, k' = bin*512 + c order
__device__ float g_fc1[(size_t)NROI * FCD];      // 8 MB (tf32-rounded)
__device__ float g_fc2[(size_t)NROI * FCD];      // 8 MB (tf32-rounded)
__device__ float g_w1t[(size_t)FCIN * FCD];      // 411 MB W1^T [N, k'] tf32
__device__ float g_w2t[(size_t)FCD * FCD];       // 67 MB  W2^T [N, k] tf32
__device__ float g_wt[(size_t)128 * FCD];        // 2 MB head weights [128, 4096] tf32, zero-padded

// ---------------- common helpers ----------------
__device__ __forceinline__ float tf32_rn(float x) {
    float r;
    asm("cvt.rna.tf32.f32 %0, %1;" : "=f"(r) : "f"(x));
    return r;
}
__device__ __forceinline__ uint32_t smem_u32(const void* p) {
    uint32_t a;
    asm("{ .reg .u64 t; cvta.to.shared.u64 t, %1; cvt.u32.u64 %0, t; }" : "=r"(a) : "l"(p));
    return a;
}
__device__ __forceinline__ void cpasync16(uint32_t dst, const void* src) {
    asm volatile("cp.async.cg.shared.global [%0], [%1], 16;" :: "r"(dst), "l"(src));
}
#define SWZ(x) ((x) ^ (((x) >> 3) & 0x70))

#if HAS_TCGEN05
__device__ __forceinline__ void mbar_init(uint32_t mbar, uint32_t cnt) {
    asm volatile("mbarrier.init.shared.b64 [%0], %1;" :: "r"(mbar), "r"(cnt) : "memory");
}
__device__ __forceinline__ void mbar_wait(uint32_t mbar, uint32_t parity) {
    asm volatile(
        "{\n\t.reg .pred P;\n"
        "LW_%=:\n\t"
        "mbarrier.try_wait.parity.acquire.cta.shared::cta.b64 P, [%0], %1, 0x989680;\n\t"
        "@P bra.uni LD_%=;\n\t"
        "bra.uni LW_%=;\n"
        "LD_%=:\n\t}"
        :: "r"(mbar), "r"(parity) : "memory");
}
__device__ __forceinline__ void cpasync_arrive(uint32_t mbar) {
    asm volatile("cp.async.mbarrier.arrive.noinc.shared.b64 [%0];" :: "r"(mbar) : "memory");
}
__device__ __forceinline__ void tmem_alloc(uint32_t smem_dst, uint32_t ncols) {
    asm volatile("tcgen05.alloc.cta_group::1.sync.aligned.shared::cta.b32 [%0], %1;"
                 :: "r"(smem_dst), "r"(ncols) : "memory");
}
__device__ __forceinline__ void tmem_dealloc(uint32_t tmem, uint32_t ncols) {
    asm volatile("tcgen05.dealloc.cta_group::1.sync.aligned.b32 %0, %1;" :: "r"(tmem), "r"(ncols));
}
__device__ __forceinline__ void tmem_relinquish() {
    asm volatile("tcgen05.relinquish_alloc_permit.cta_group::1.sync.aligned;");
}
__device__ __forceinline__ void tcommit(uint32_t mbar) {
    asm volatile("tcgen05.commit.cta_group::1.mbarrier::arrive::one.shared::cluster.b64 [%0];"
                 :: "r"(mbar) : "memory");
}
__device__ __forceinline__ void tc_fence_after() {
    asm volatile("tcgen05.fence::after_thread_sync;" ::: "memory");
}
__device__ __forceinline__ void fence_async_smem() {
    asm volatile("fence.proxy.async.shared::cta;" ::: "memory");
}
__device__ __forceinline__ void mma_tf32(uint32_t d, uint64_t ad, uint64_t bd,
                                         uint32_t idesc, uint32_t accum) {
    asm volatile(
        "{\n\t.reg .pred p;\n\t"
        "setp.ne.u32 p, %4, 0;\n\t"
        "tcgen05.mma.cta_group::1.kind::tf32 [%0], %1, %2, %3, {%5, %5, %5, %5}, p;\n\t}"
        :: "r"(d), "l"(ad), "l"(bd), "r"(idesc), "r"(accum), "r"(0u) : "memory");
}
__device__ __forceinline__ void ldtm_x32(uint32_t* r, uint32_t ta) {
    asm volatile(
        "tcgen05.ld.sync.aligned.32x32b.x32.b32 "
        "{%0,%1,%2,%3,%4,%5,%6,%7,%8,%9,%10,%11,%12,%13,%14,%15,"
        "%16,%17,%18,%19,%20,%21,%22,%23,%24,%25,%26,%27,%28,%29,%30,%31}, [%32];"
        : "=r"(r[0]), "=r"(r[1]), "=r"(r[2]), "=r"(r[3]), "=r"(r[4]), "=r"(r[5]), "=r"(r[6]), "=r"(r[7]),
          "=r"(r[8]), "=r"(r[9]), "=r"(r[10]), "=r"(r[11]), "=r"(r[12]), "=r"(r[13]), "=r"(r[14]), "=r"(r[15]),
          "=r"(r[16]), "=r"(r[17]), "=r"(r[18]), "=r"(r[19]), "=r"(r[20]), "=r"(r[21]), "=r"(r[22]), "=r"(r[23]),
          "=r"(r[24]), "=r"(r[25]), "=r"(r[26]), "=r"(r[27]), "=r"(r[28]), "=r"(r[29]), "=r"(r[30]), "=r"(r[31])
        : "r"(ta));
}
#define LDTM_WAIT() asm volatile("tcgen05.wait::ld.sync.aligned;" ::: "memory")

// K-major SW128 descriptor: LBO=1, SBO=64, version=1
static constexpr uint64_t DESC_K =
    (2ULL << 61) | (1ULL << 46) | (64ULL << 32) | (1ULL << 16);
// idesc: F32 acc, tf32 a/b, K-major both, M=128, N=128
static constexpr uint32_t IDESC_TF32_N128 = 0x8200910u;
#endif  // HAS_TCGEN05

#define NSTAGE 6
#define SM_TOTAL 197760        // 1152 header/align + 6 x 32KB stages

// ---------------- x transpose: x[c][p] -> xT[p][c] ----------------
__global__ __launch_bounds__(256)
void xt_kernel(const float* __restrict__ x, float* __restrict__ xT)
{
    __shared__ float t[32][33];
    int pb = blockIdx.x * 32, cb = blockIdx.y * 32;
    int tx = threadIdx.x & 31, ty = threadIdx.x >> 5;
    #pragma unroll
    for (int i = 0; i < 32; i += 8) {
        int p = pb + tx;
        if (p < HWP) t[ty + i][tx] = x[(size_t)(cb + ty + i) * HWP + p];
    }
    __syncthreads();
    #pragma unroll
    for (int i = 0; i < 32; i += 8) {
        int p = pb + ty + i;
        if (p < HWP) xT[(size_t)p * CCH + cb + tx] = t[tx][ty + i];
    }
}

// ---------------- RoI adaptive max pool (float4, 2 rois/block) ----------------
// 256 threads: lanes 0-127 -> roi A, 128-255 -> roi B. Each lane owns 4 channels.
__global__ __launch_bounds__(256)
void roi_pool_kernel(const float* __restrict__ xT,
                     const float* __restrict__ rois,
                     float* __restrict__ pool)
{
    int half = threadIdx.x >> 7;           // 0/1: which roi
    int lane = threadIdx.x & 127;          // channel group
    int n = blockIdx.x * 2 + half;
    __shared__ int rs[2][7], re[2][7], cs[2][7], ce[2][7];
    if (lane == 0) {
        int x1 = (int)(rois[n * 4 + 0] * 0.0625f);
        int y1 = (int)(rois[n * 4 + 1] * 0.0625f);
        int x2 = (int)(rois[n * 4 + 2] * 0.0625f);
        int y2 = (int)(rois[n * 4 + 3] * 0.0625f);
        int h = y2 - y1 + 1;
        int w = x2 - x1 + 1;
        #pragma unroll
        for (int p = 0; p < 7; p++) {
            rs[half][p] = y1 + (p * h) / 7;
            re[half][p] = y1 + ((p + 1) * h + 6) / 7;
            cs[half][p] = x1 + (p * w) / 7;
            ce[half][p] = x1 + ((p + 1) * w + 6) / 7;
        }
    }
    __syncthreads();

    const float4* xp = (const float4*)xT;          // row p -> index p*128 + lane
    float* out = pool + (size_t)n * FCIN + lane * 4;
    #pragma unroll
    for (int ph = 0; ph < 7; ph++) {
        #pragma unroll
        for (int pw = 0; pw < 7; pw++) {
            float4 m = make_float4(-CUDART_INF_F, -CUDART_INF_F,
                                   -CUDART_INF_F, -CUDART_INF_F);
            for (int y = rs[half][ph]; y < re[half][ph]; y++) {
                const float4* row = xp + (size_t)(y * WF) * 128 + lane;
                for (int xx = cs[half][pw]; xx < ce[half][pw]; xx++) {
                    float4 v = row[(size_t)xx * 128];
                    m.x = fmaxf(m.x, v.x); m.y = fmaxf(m.y, v.y);
                    m.z = fmaxf(m.z, v.z); m.w = fmaxf(m.w, v.w);
                }
            }
            float4 o = make_float4(tf32_rn(m.x), tf32_rn(m.y),
                                   tf32_rn(m.z), tf32_rn(m.w));
            *(float4*)(out + (ph * 7 + pw) * 512) = o;
        }
    }
}

// ---------------- transpose + round (optional k-permute): Wt[n][kp] = rn(W[perm(kp)][n]) ----------------
template <bool PERM>
__global__ __launch_bounds__(256)
void transpose_round_kernel(const float* __restrict__ W, float* __restrict__ Wt,
                            int K, int N)
{
    __shared__ float t[32][33];
    int kb = blockIdx.y * 32, nb = blockIdx.x * 32;
    int tx = threadIdx.x & 31, ty = threadIdx.x >> 5;
    #pragma unroll
    for (int i = 0; i < 32; i += 8) {
        int kp = kb + ty + i;
        int k = PERM ? ((kp & 511) * 49 + (kp >> 9)) : kp;
        t[ty + i][tx] = tf32_rn(W[(size_t)k * N + nb + tx]);
    }
    __syncthreads();
    #pragma unroll
    for (int i = 0; i < 32; i += 8)
        Wt[(size_t)(nb + ty + i) * K + kb + tx] = t[tx][ty + i];
}

// ---------------- head weight transpose: Wt[128][4096] tf32, zero-padded ----------------
__global__ void transpose_head_kernel(const float* __restrict__ Wl,
                                      const float* __restrict__ Ws,
                                      float* __restrict__ Wt)
{
    int idx = blockIdx.x * 256 + threadIdx.x;      // o*4096 + k, o in [0,128)
    if (idx >= 128 * FCD) return;
    int o = idx >> 12, k = idx & 4095;
    float v = 0.f;
    if (o < NLOC)       v = Wl[(size_t)k * NLOC + o];
    else if (o < NHEAD) v = Ws[(size_t)k * NSC + (o - NLOC)];
    Wt[idx] = tf32_rn(v);
}

// ---------------- warp-specialized tcgen05 tf32 GEMM ----------------
// C = relu(A[512,K] @ Bt[GN,K]^T + bias). HEAD variant maps cols to loc/score outputs.
// warps 0-3: cp.async producers; tid 128: MMA issuer; warps 4-7: epilogue.
template <bool RELU, bool ROUND_OUT, bool HEAD>
__global__ __launch_bounds__(256, 1)
void gemm_kernel(int K,
                 const float* __restrict__ A,
                 const float* __restrict__ Bt,
                 const float* __restrict__ bias,   // HEAD: b_loc
                 const float* __restrict__ bias2,  // HEAD: b_score (else null)
                 float* __restrict__ C,            // HEAD: out_loc
                 float* __restrict__ C2)           // HEAD: out_score (else null)
{
    extern __shared__ char smem[];
    const int tid = threadIdx.x;
    const int m0 = blockIdx.y * 128;
    const int n0 = blockIdx.x * 128;

#if HAS_TCGEN05
    const uint32_t sbase = smem_u32(smem);
    const uint32_t ubase = (sbase + 128 + 1023) & ~1023u;
    const int wid = tid >> 5, lid = tid & 31;
    const int nt = K >> 5;
    const uint32_t mb_full  = sbase + 16;
    const uint32_t mb_empty = sbase + 64;
    const uint32_t mb_done  = sbase + 120;

    if (tid == 0) {
        #pragma unroll
        for (int s = 0; s < NSTAGE; s++) {
            mbar_init(mb_full + s * 8, 128);   // 128 producer threads
            mbar_init(mb_empty + s * 8, 1);
        }
        mbar_init(mb_done, 1);
    }
    if (wid == 0) {
        tmem_alloc(sbase, 128);
        tmem_relinquish();
    }
    __syncthreads();
    const uint32_t tmem = *(const volatile uint32_t*)smem;

    const float* Abase = A  + (size_t)m0 * K;
    const float* Bbase = Bt + (size_t)n0 * K;

    if (wid < 4) {
        // ---------------- producers ----------------
        for (int t = 0; t < nt; t++) {
            int s = t - (t / NSTAGE) * NSTAGE;
            if (t >= NSTAGE)
                mbar_wait(mb_empty + s * 8, (t / NSTAGE - 1) & 1);
            uint32_t dA = ubase + s * 32768;
            uint32_t dB = dA + 16384;
            const float* Ab = Abase + (size_t)t * 32;
            const float* Bb = Bbase + (size_t)t * 32;
            #pragma unroll
            for (int i = 0; i < 8; i++) {
                int idx = tid + i * 128;
                int row = idx >> 3, c = idx & 7;
                cpasync16(dA + SWZ(row * 128 + c * 16), Ab + (size_t)row * K + c * 4);
            }
            #pragma unroll
            for (int i = 0; i < 8; i++) {
                int idx = tid + i * 128;
                int row = idx >> 3, c = idx & 7;
                cpasync16(dB + SWZ(row * 128 + c * 16), Bb + (size_t)row * K + c * 4);
            }
            cpasync_arrive(mb_full + s * 8);
        }
    } else if (tid == 128) {
        // ---------------- MMA issuer ----------------
        for (int t = 0; t < nt; t++) {
            int s = t - (t / NSTAGE) * NSTAGE;
            mbar_wait(mb_full + s * 8, (t / NSTAGE) & 1);
            fence_async_smem();
            tc_fence_after();
            uint32_t aaddr = ubase + s * 32768;
            uint32_t baddr = aaddr + 16384;
            uint64_t ad = DESC_K | ((aaddr >> 4) & 0x3FFF);
            uint64_t bd = DESC_K | ((baddr >> 4) & 0x3FFF);
            #pragma unroll
            for (int ks = 0; ks < 4; ks++)     // 4 K-steps of 8 (32B each)
                mma_tf32(tmem, ad + ks * 2, bd + ks * 2,
                         IDESC_TF32_N128, (t > 0 || ks > 0) ? 1u : 0u);
            tcommit(mb_empty + s * 8);
        }
        tcommit(mb_done);
    }

    // ---------------- epilogue ----------------
    mbar_wait(mb_done, 0);
    __syncthreads();
    tc_fence_after();
    if (wid >= 4) {
        int m = m0 + (wid & 3) * 32 + lid;
        #pragma unroll
        for (int cb = 0; cb < 4; cb++) {
            uint32_t r[32];
            ldtm_x32(r, tmem + cb * 32);
            LDTM_WAIT();
            if (HEAD) {
                #pragma unroll
                for (int i = 0; i < 32; i++) {
                    int n = cb * 32 + i;
                    float v = __uint_as_float(r[i]);
                    if (n < NLOC)
                        C[(size_t)m * NLOC + n] = v + bias[n];
                    else if (n < NHEAD)
                        C2[(size_t)m * NSC + (n - NLOC)] = v + bias2[n - NLOC];
                }
            } else {
                float* Crow = C + (size_t)m * GN + n0 + cb * 32;
                const float* brow = bias + n0 + cb * 32;
                #pragma unroll
                for (int i = 0; i < 32; i++) {
                    float v = __uint_as_float(r[i]) + brow[i];
                    if (RELU) v = fmaxf(v, 0.f);
                    if (ROUND_OUT) v = tf32_rn(v);
                    Crow[i] = v;
                }
            }
        }
    }
    __syncthreads();
    if (wid == 0) tmem_dealloc(tmem, 128);

#else  // ---------------- fp32 fallback (non-103a pass; Bt[n][k]) ----------------
    float* As = (float*)smem;                 // [16][132]
    float* Bs = (float*)smem + 16 * 132;      // [128][18]
    const int tx = tid & 15;
    const int ty = tid >> 4;

    float acc[8][8];
    #pragma unroll
    for (int i = 0; i < 8; i++)
        #pragma unroll
        for (int j = 0; j < 8; j++) acc[i][j] = 0.f;

    const float* Ablk = A  + (size_t)m0 * K;
    const float* Bblk = Bt + (size_t)n0 * K;

    for (int k0 = 0; k0 < K; k0 += 16) {
        #pragma unroll
        for (int t = 0; t < 2; t++) {
            int idx = tid + t * 256;
            int row = idx >> 2;
            int kc  = (idx & 3) * 4;
            float4 v = *(const float4*)(Ablk + (size_t)row * K + k0 + kc);
            As[(kc + 0) * 132 + row] = v.x;
            As[(kc + 1) * 132 + row] = v.y;
            As[(kc + 2) * 132 + row] = v.z;
            As[(kc + 3) * 132 + row] = v.w;
        }
        #pragma unroll
        for (int t = 0; t < 2; t++) {
            int idx = tid + t * 256;
            int row = idx >> 2;
            int kc  = (idx & 3) * 4;
            float4 v = *(const float4*)(Bblk + (size_t)row * K + k0 + kc);
            Bs[row * 18 + kc + 0] = v.x;
            Bs[row * 18 + kc + 1] = v.y;
            Bs[row * 18 + kc + 2] = v.z;
            Bs[row * 18 + kc + 3] = v.w;
        }
        __syncthreads();

        #pragma unroll
        for (int k = 0; k < 16; k++) {
            float a[8], b[8];
            *(float4*)&a[0] = *(const float4*)&As[k * 132 + ty * 8 + 0];
            *(float4*)&a[4] = *(const float4*)&As[k * 132 + ty * 8 + 4];
            #pragma unroll
            for (int j = 0; j < 8; j++) b[j] = Bs[(tx * 8 + j) * 18 + k];
            #pragma unroll
            for (int i = 0; i < 8; i++)
                #pragma unroll
                for (int j = 0; j < 8; j++)
                    acc[i][j] = fmaf(a[i], b[j], acc[i][j]);
        }
        __syncthreads();
    }

    #pragma unroll
    for (int i = 0; i < 8; i++) {
        int m = m0 + ty * 8 + i;
        #pragma unroll
        for (int j = 0; j < 8; j++) {
            int n = n0 + tx * 8 + j;
            if (HEAD) {
                float v = acc[i][j];
                if (n < NLOC)
                    C[(size_t)m * NLOC + n] = v + bias[n];
                else if (n < NHEAD)
                    C2[(size_t)m * NSC + (n - NLOC)] = v + bias2[n - NLOC];
            } else {
                float v = acc[i][j] + bias[n];
                if (RELU) v = fmaxf(v, 0.f);
                if (ROUND_OUT) v = tf32_rn(v);
                C[(size_t)m * GN + n] = v;
            }
        }
    }
#endif
}

// ---------------- launch ----------------
extern "C" void kernel_launch(void* const* d_in, const int* in_sizes, int n_in,
                              void* d_out, int out_size)
{
    const float* x      = (const float*)d_in[0];
    const float* rois   = (const float*)d_in[1];
    const float* W1     = (const float*)d_in[2];
    const float* b1     = (const float*)d_in[3];
    const float* W2     = (const float*)d_in[4];
    const float* b2     = (const float*)d_in[5];
    const float* W_loc  = (const float*)d_in[6];
    const float* b_loc  = (const float*)d_in[7];
    const float* W_sc   = (const float*)d_in[8];
    const float* b_sc   = (const float*)d_in[9];
    float* out = (float*)d_out;

    float *p_xt, *p_pool, *p_fc1, *p_fc2, *p_wt, *p_w1t, *p_w2t;
    cudaGetSymbolAddress((void**)&p_xt,   g_xt);
    cudaGetSymbolAddress((void**)&p_pool, g_pool);
    cudaGetSymbolAddress((void**)&p_fc1,  g_fc1);
    cudaGetSymbolAddress((void**)&p_fc2,  g_fc2);
    cudaGetSymbolAddress((void**)&p_wt,   g_wt);
    cudaGetSymbolAddress((void**)&p_w1t,  g_w1t);
    cudaGetSymbolAddress((void**)&p_w2t,  g_w2t);

    cudaFuncSetAttribute(gemm_kernel<true, true, false>,
                         cudaFuncAttributeMaxDynamicSharedMemorySize, SM_TOTAL);
    cudaFuncSetAttribute(gemm_kernel<false, false, true>,
                         cudaFuncAttributeMaxDynamicSharedMemorySize, SM_TOTAL);

    // 0) x -> xT[p][c]; weights -> Wt[n][k] (tf32; W1 with k-permutation); head Wt padded
    {
        dim3 gx((HWP + 31) / 32, CCH / 32);
        xt_kernel<<<gx, 256>>>(x, p_xt);
        dim3 gt1(FCD / 32, FCIN / 32);
        transpose_round_kernel<true><<<gt1, 256>>>(W1, p_w1t, FCIN, FCD);
        dim3 gt2(FCD / 32, FCD / 32);
        transpose_round_kernel<false><<<gt2, 256>>>(W2, p_w2t, FCD, FCD);
        transpose_head_kernel<<<(128 * FCD) / 256, 256>>>(W_loc, W_sc, p_wt);
    }

    // 1) RoI adaptive max pool (float4 lanes, bin-major k')
    roi_pool_kernel<<<NROI / 2, 256>>>(p_xt, rois, p_pool);

    // 2) fc1 = relu(pool @ W1 + b1)   K = 25088
    dim3 g(GN / 128, NROI / 128);
    gemm_kernel<true, true, false><<<g, 256, SM_TOTAL>>>(
        FCIN, p_pool, p_w1t, b1, nullptr, p_fc1, nullptr);

    // 3) fc2 = relu(fc1 @ W2 + b2)   K = 4096 (tf32-rounded for head GEMM)
    gemm_kernel<true, true, false><<<g, 256, SM_TOTAL>>>(
        FCD, p_fc1, p_w2t, b2, nullptr, p_fc2, nullptr);

    // 4) head GEMM: [512,4096] @ [128,4096]^T -> loc/score, N=128 (padded)
    dim3 gh(1, NROI / 128);
    gemm_kernel<false, false, true><<<gh, 256, SM_TOTAL>>>(
        FCD, p_fc2, p_wt, b_loc, b_sc, out, out + (size_t)NROI * NLOC);
}

// round 17
// speedup vs baseline: 2.0728x; 1.0676x over previous
#include <cuda_runtime.h>
#include <cstdint>
#include <math_constants.h>

// ---------------- problem constants ----------------
#define CCH 512
#define HF 50
#define WF 75
#define HWP (HF * WF)          // 3750
#define NROI 512
#define FCIN 25088
#define FCD 4096
#define GN 4096
#define NLOC 84
#define NSC 21
#define NHEAD 105

#if defined(__CUDA_ARCH__) && defined(__CUDA_ARCH_FEAT_SM103_ALL)
#define HAS_TCGEN05 1
#else
#define HAS_TCGEN05 0
#endif

// ---------------- device scratch ----------------
__device__ float g_xt[(size_t)HWP * CCH];        // 7.7 MB x transposed [h*w][c]
__device__ float g_pool[(size_t)NROI * FCIN];    // 51.4 MB, k' = bin*512 + c order
__device__ float g_fc1[(size_t)NROI * FCD];      // 8 MB (tf32-rounded)
__device__ float g_fc2[(size_t)NROI * FCD];      // 8 MB (tf32-rounded)
__device__ float g_w1t[(size_t)FCIN * FCD];      // 411 MB W1^T [N, k'] tf32
__device__ float g_w2t[(size_t)FCD * FCD];       // 67 MB  W2^T [N, k] tf32
__device__ float g_wt[(size_t)128 * FCD];        // 2 MB head weights [128,4096] tf32 padded

// ---------------- common helpers ----------------
__device__ __forceinline__ float tf32_rn(float x) {
    float r;
    asm("cvt.rna.tf32.f32 %0, %1;" : "=f"(r) : "f"(x));
    return r;
}
__device__ __forceinline__ uint32_t smem_u32(const void* p) {
    uint32_t a;
    asm("{ .reg .u64 t; cvta.to.shared.u64 t, %1; cvt.u32.u64 %0, t; }" : "=r"(a) : "l"(p));
    return a;
}
__device__ __forceinline__ void cpasync16(uint32_t dst, const void* src) {
    asm volatile("cp.async.cg.shared.global [%0], [%1], 16;" :: "r"(dst), "l"(src));
}
#define SWZ(x) ((x) ^ (((x) >> 3) & 0x70))

#if HAS_TCGEN05
__device__ __forceinline__ void mbar_init(uint32_t mbar, uint32_t cnt) {
    asm volatile("mbarrier.init.shared.b64 [%0], %1;" :: "r"(mbar), "r"(cnt) : "memory");
}
__device__ __forceinline__ void mbar_wait(uint32_t mbar, uint32_t parity) {
    asm volatile(
        "{\n\t.reg .pred P;\n"
        "LW_%=:\n\t"
        "mbarrier.try_wait.parity.acquire.cta.shared::cta.b64 P, [%0], %1, 0x989680;\n\t"
        "@P bra.uni LD_%=;\n\t"
        "bra.uni LW_%=;\n"
        "LD_%=:\n\t}"
        :: "r"(mbar), "r"(parity) : "memory");
}
__device__ __forceinline__ void cpasync_arrive(uint32_t mbar) {
    asm volatile("cp.async.mbarrier.arrive.noinc.shared.b64 [%0];" :: "r"(mbar) : "memory");
}
__device__ __forceinline__ void tmem_alloc(uint32_t smem_dst, uint32_t ncols) {
    asm volatile("tcgen05.alloc.cta_group::1.sync.aligned.shared::cta.b32 [%0], %1;"
                 :: "r"(smem_dst), "r"(ncols) : "memory");
}
__device__ __forceinline__ void tmem_dealloc(uint32_t tmem, uint32_t ncols) {
    asm volatile("tcgen05.dealloc.cta_group::1.sync.aligned.b32 %0, %1;" :: "r"(tmem), "r"(ncols));
}
__device__ __forceinline__ void tmem_relinquish() {
    asm volatile("tcgen05.relinquish_alloc_permit.cta_group::1.sync.aligned;");
}
__device__ __forceinline__ void tcommit(uint32_t mbar) {
    asm volatile("tcgen05.commit.cta_group::1.mbarrier::arrive::one.shared::cluster.b64 [%0];"
                 :: "r"(mbar) : "memory");
}
__device__ __forceinline__ void tc_fence_after() {
    asm volatile("tcgen05.fence::after_thread_sync;" ::: "memory");
}
__device__ __forceinline__ void fence_async_smem() {
    asm volatile("fence.proxy.async.shared::cta;" ::: "memory");
}
__device__ __forceinline__ void mma_tf32(uint32_t d, uint64_t ad, uint64_t bd,
                                         uint32_t idesc, uint32_t accum) {
    asm volatile(
        "{\n\t.reg .pred p;\n\t"
        "setp.ne.u32 p, %4, 0;\n\t"
        "tcgen05.mma.cta_group::1.kind::tf32 [%0], %1, %2, %3, {%5, %5, %5, %5}, p;\n\t}"
        :: "r"(d), "l"(ad), "l"(bd), "r"(idesc), "r"(accum), "r"(0u) : "memory");
}
__device__ __forceinline__ void ldtm_x32(uint32_t* r, uint32_t ta) {
    asm volatile(
        "tcgen05.ld.sync.aligned.32x32b.x32.b32 "
        "{%0,%1,%2,%3,%4,%5,%6,%7,%8,%9,%10,%11,%12,%13,%14,%15,"
        "%16,%17,%18,%19,%20,%21,%22,%23,%24,%25,%26,%27,%28,%29,%30,%31}, [%32];"
        : "=r"(r[0]), "=r"(r[1]), "=r"(r[2]), "=r"(r[3]), "=r"(r[4]), "=r"(r[5]), "=r"(r[6]), "=r"(r[7]),
          "=r"(r[8]), "=r"(r[9]), "=r"(r[10]), "=r"(r[11]), "=r"(r[12]), "=r"(r[13]), "=r"(r[14]), "=r"(r[15]),
          "=r"(r[16]), "=r"(r[17]), "=r"(r[18]), "=r"(r[19]), "=r"(r[20]), "=r"(r[21]), "=r"(r[22]), "=r"(r[23]),
          "=r"(r[24]), "=r"(r[25]), "=r"(r[26]), "=r"(r[27]), "=r"(r[28]), "=r"(r[29]), "=r"(r[30]), "=r"(r[31])
        : "r"(ta));
}
#define LDTM_WAIT() asm volatile("tcgen05.wait::ld.sync.aligned;" ::: "memory")

// K-major SW128 descriptor: LBO=1, SBO=64, version=1
static constexpr uint64_t DESC_K =
    (2ULL << 61) | (1ULL << 46) | (64ULL << 32) | (1ULL << 16);
// idesc: F32 acc, tf32 a/b, K-major both, M=128, N=128
static constexpr uint32_t IDESC_TF32_N128 = 0x8200910u;
#endif  // HAS_TCGEN05

#define NSTAGE 3               // 3 stages x 64KB (A 32KB + B 32KB, K-tile 64)
#define SM_TOTAL 197760        // 1152 header/align + 3 x 65536

// ---------------- x transpose: x[c][p] -> xT[p][c] ----------------
__global__ __launch_bounds__(256)
void xt_kernel(const float* __restrict__ x, float* __restrict__ xT)
{
    __shared__ float t[32][33];
    int pb = blockIdx.x * 32, cb = blockIdx.y * 32;
    int tx = threadIdx.x & 31, ty = threadIdx.x >> 5;
    #pragma unroll
    for (int i = 0; i < 32; i += 8) {
        int p = pb + tx;
        if (p < HWP) t[ty + i][tx] = x[(size_t)(cb + ty + i) * HWP + p];
    }
    __syncthreads();
    #pragma unroll
    for (int i = 0; i < 32; i += 8) {
        int p = pb + ty + i;
        if (p < HWP) xT[(size_t)p * CCH + cb + tx] = t[tx][ty + i];
    }
}

// ---------------- prep sub-kernels (device funcs, dispatched by block id) ----------------
__device__ void pool_block(int bid, const float* __restrict__ xT,
                           const float* __restrict__ rois, float* __restrict__ pool)
{
    int half = threadIdx.x >> 7;
    int lane = threadIdx.x & 127;
    int n = bid * 2 + half;
    __shared__ int rs[2][7], re[2][7], cs[2][7], ce[2][7];
    if (lane == 0) {
        int x1 = (int)(rois[n * 4 + 0] * 0.0625f);
        int y1 = (int)(rois[n * 4 + 1] * 0.0625f);
        int x2 = (int)(rois[n * 4 + 2] * 0.0625f);
        int y2 = (int)(rois[n * 4 + 3] * 0.0625f);
        int h = y2 - y1 + 1;
        int w = x2 - x1 + 1;
        #pragma unroll
        for (int p = 0; p < 7; p++) {
            rs[half][p] = y1 + (p * h) / 7;
            re[half][p] = y1 + ((p + 1) * h + 6) / 7;
            cs[half][p] = x1 + (p * w) / 7;
            ce[half][p] = x1 + ((p + 1) * w + 6) / 7;
        }
    }
    __syncthreads();

    const float4* xp = (const float4*)xT;
    float* out = pool + (size_t)n * FCIN + lane * 4;
    #pragma unroll
    for (int ph = 0; ph < 7; ph++) {
        #pragma unroll
        for (int pw = 0; pw < 7; pw++) {
            float4 m = make_float4(-CUDART_INF_F, -CUDART_INF_F,
                                   -CUDART_INF_F, -CUDART_INF_F);
            for (int y = rs[half][ph]; y < re[half][ph]; y++) {
                const float4* row = xp + (size_t)(y * WF) * 128 + lane;
                for (int xx = cs[half][pw]; xx < ce[half][pw]; xx++) {
                    float4 v = row[(size_t)xx * 128];
                    m.x = fmaxf(m.x, v.x); m.y = fmaxf(m.y, v.y);
                    m.z = fmaxf(m.z, v.z); m.w = fmaxf(m.w, v.w);
                }
            }
            float4 o = make_float4(tf32_rn(m.x), tf32_rn(m.y),
                                   tf32_rn(m.z), tf32_rn(m.w));
            *(float4*)(out + (ph * 7 + pw) * 512) = o;
        }
    }
}

template <bool PERM>
__device__ void wtrans_block(int bx, int by, const float* __restrict__ W,
                             float* __restrict__ Wt, int K, int N)
{
    __shared__ float t[32][33];
    int kb = by * 32, nb = bx * 32;
    int tx = threadIdx.x & 31, ty = threadIdx.x >> 5;
    #pragma unroll
    for (int i = 0; i < 32; i += 8) {
        int kp = kb + ty + i;
        int k = PERM ? ((kp & 511) * 49 + (kp >> 9)) : kp;
        t[ty + i][tx] = tf32_rn(W[(size_t)k * N + nb + tx]);
    }
    __syncthreads();
    #pragma unroll
    for (int i = 0; i < 32; i += 8)
        Wt[(size_t)(nb + ty + i) * K + kb + tx] = t[tx][ty + i];
}

__device__ void headw_block(int bid, const float* __restrict__ Wl,
                            const float* __restrict__ Ws, float* __restrict__ Wt)
{
    int idx = bid * 256 + threadIdx.x;             // o*4096 + k
    int o = idx >> 12, k = idx & 4095;
    float v = 0.f;
    if (o < NLOC)       v = Wl[(size_t)k * NLOC + o];
    else if (o < NHEAD) v = Ws[(size_t)k * NSC + (o - NLOC)];
    Wt[idx] = tf32_rn(v);
}

// fused prep: pool (256) | W1t (100352) | W2t (16384) | headT (2048)
#define PREP_POOL   256
#define PREP_W1     100352
#define PREP_W2     16384
#define PREP_HEAD   2048
__global__ __launch_bounds__(256)
void prep_kernel(const float* __restrict__ xT, const float* __restrict__ rois,
                 float* __restrict__ pool,
                 const float* __restrict__ W1, float* __restrict__ W1t,
                 const float* __restrict__ W2, float* __restrict__ W2t,
                 const float* __restrict__ Wl, const float* __restrict__ Ws,
                 float* __restrict__ Wh)
{
    int b = blockIdx.x;
    if (b < PREP_POOL) {
        pool_block(b, xT, rois, pool);
        return;
    }
    b -= PREP_POOL;
    if (b < PREP_W1) {
        wtrans_block<true>(b % 128, b / 128, W1, W1t, FCIN, FCD);
        return;
    }
    b -= PREP_W1;
    if (b < PREP_W2) {
        wtrans_block<false>(b % 128, b / 128, W2, W2t, FCD, FCD);
        return;
    }
    b -= PREP_W2;
    headw_block(b, Wl, Ws, Wh);
}

// ---------------- warp-specialized tcgen05 tf32 GEMM, K-tile 64 ----------------
// C = relu(A[512,K] @ Bt[GN,K]^T + bias). HEAD maps cols to loc/score outputs.
// warps 0-3: cp.async producers; tid 128: MMA issuer; warps 4-7: epilogue.
template <bool RELU, bool ROUND_OUT, bool HEAD>
__global__ __launch_bounds__(256, 1)
void gemm_kernel(int K,
                 const float* __restrict__ A,
                 const float* __restrict__ Bt,
                 const float* __restrict__ bias,   // HEAD: b_loc
                 const float* __restrict__ bias2,  // HEAD: b_score
                 float* __restrict__ C,            // HEAD: out_loc
                 float* __restrict__ C2)           // HEAD: out_score
{
    extern __shared__ char smem[];
    const int tid = threadIdx.x;
    const int m0 = blockIdx.y * 128;
    const int n0 = blockIdx.x * 128;

#if HAS_TCGEN05
    const uint32_t sbase = smem_u32(smem);
    const uint32_t ubase = (sbase + 128 + 1023) & ~1023u;
    const int wid = tid >> 5, lid = tid & 31;
    const int nt = K >> 6;                         // K-tile 64
    const uint32_t mb_full  = sbase + 16;
    const uint32_t mb_empty = sbase + 64;
    const uint32_t mb_done  = sbase + 120;

    if (tid == 0) {
        #pragma unroll
        for (int s = 0; s < NSTAGE; s++) {
            mbar_init(mb_full + s * 8, 128);
            mbar_init(mb_empty + s * 8, 1);
        }
        mbar_init(mb_done, 1);
    }
    if (wid == 0) {
        tmem_alloc(sbase, 128);
        tmem_relinquish();
    }
    __syncthreads();
    const uint32_t tmem = *(const volatile uint32_t*)smem;

    const float* Abase = A  + (size_t)m0 * K;
    const float* Bbase = Bt + (size_t)n0 * K;

    if (wid < 4) {
        // ---------------- producers: per stage 64KB = A(2x16KB) + B(2x16KB) ----------------
        for (int t = 0; t < nt; t++) {
            int s = t - (t / NSTAGE) * NSTAGE;
            if (t >= NSTAGE)
                mbar_wait(mb_empty + s * 8, (t / NSTAGE - 1) & 1);
            uint32_t dA = ubase + s * 65536;
            uint32_t dB = dA + 32768;
            #pragma unroll
            for (int c = 0; c < 2; c++) {
                const float* Ab = Abase + (size_t)t * 64 + c * 32;
                const float* Bb = Bbase + (size_t)t * 64 + c * 32;
                uint32_t dAc = dA + c * 16384;
                uint32_t dBc = dB + c * 16384;
                #pragma unroll
                for (int i = 0; i < 8; i++) {
                    int idx = tid + i * 128;
                    int row = idx >> 3, cc = idx & 7;
                    cpasync16(dAc + SWZ(row * 128 + cc * 16), Ab + (size_t)row * K + cc * 4);
                }
                #pragma unroll
                for (int i = 0; i < 8; i++) {
                    int idx = tid + i * 128;
                    int row = idx >> 3, cc = idx & 7;
                    cpasync16(dBc + SWZ(row * 128 + cc * 16), Bb + (size_t)row * K + cc * 4);
                }
            }
            cpasync_arrive(mb_full + s * 8);
        }
    } else if (tid == 128) {
        // ---------------- MMA issuer: 8 dispatches per 64-K tile ----------------
        for (int t = 0; t < nt; t++) {
            int s = t - (t / NSTAGE) * NSTAGE;
            mbar_wait(mb_full + s * 8, (t / NSTAGE) & 1);
            fence_async_smem();
            tc_fence_after();
            uint32_t aaddr = ubase + s * 65536;
            uint32_t baddr = aaddr + 32768;
            #pragma unroll
            for (int c = 0; c < 2; c++) {
                uint64_t ad = DESC_K | (((aaddr + c * 16384) >> 4) & 0x3FFF);
                uint64_t bd = DESC_K | (((baddr + c * 16384) >> 4) & 0x3FFF);
                #pragma unroll
                for (int ks = 0; ks < 4; ks++)
                    mma_tf32(tmem, ad + ks * 2, bd + ks * 2,
                             IDESC_TF32_N128, (t > 0 || c > 0 || ks > 0) ? 1u : 0u);
            }
            tcommit(mb_empty + s * 8);
        }
        tcommit(mb_done);
    }

    // ---------------- epilogue ----------------
    mbar_wait(mb_done, 0);
    __syncthreads();
    tc_fence_after();
    if (wid >= 4) {
        int m = m0 + (wid & 3) * 32 + lid;
        #pragma unroll
        for (int cb = 0; cb < 4; cb++) {
            uint32_t r[32];
            ldtm_x32(r, tmem + cb * 32);
            LDTM_WAIT();
            if (HEAD) {
                #pragma unroll
                for (int i = 0; i < 32; i++) {
                    int n = cb * 32 + i;
                    float v = __uint_as_float(r[i]);
                    if (n < NLOC)
                        C[(size_t)m * NLOC + n] = v + bias[n];
                    else if (n < NHEAD)
                        C2[(size_t)m * NSC + (n - NLOC)] = v + bias2[n - NLOC];
                }
            } else {
                float* Crow = C + (size_t)m * GN + n0 + cb * 32;
                const float* brow = bias + n0 + cb * 32;
                #pragma unroll
                for (int i = 0; i < 32; i++) {
                    float v = __uint_as_float(r[i]) + brow[i];
                    if (RELU) v = fmaxf(v, 0.f);
                    if (ROUND_OUT) v = tf32_rn(v);
                    Crow[i] = v;
                }
            }
        }
    }
    __syncthreads();
    if (wid == 0) tmem_dealloc(tmem, 128);

#else  // ---------------- fp32 fallback (non-103a pass; Bt[n][k]) ----------------
    float* As = (float*)smem;                 // [16][132]
    float* Bs = (float*)smem + 16 * 132;      // [128][18]
    const int tx = tid & 15;
    const int ty = tid >> 4;

    float acc[8][8];
    #pragma unroll
    for (int i = 0; i < 8; i++)
        #pragma unroll
        for (int j = 0; j < 8; j++) acc[i][j] = 0.f;

    const float* Ablk = A  + (size_t)m0 * K;
    const float* Bblk = Bt + (size_t)n0 * K;

    for (int k0 = 0; k0 < K; k0 += 16) {
        #pragma unroll
        for (int t = 0; t < 2; t++) {
            int idx = tid + t * 256;
            int row = idx >> 2;
            int kc  = (idx & 3) * 4;
            float4 v = *(const float4*)(Ablk + (size_t)row * K + k0 + kc);
            As[(kc + 0) * 132 + row] = v.x;
            As[(kc + 1) * 132 + row] = v.y;
            As[(kc + 2) * 132 + row] = v.z;
            As[(kc + 3) * 132 + row] = v.w;
        }
        #pragma unroll
        for (int t = 0; t < 2; t++) {
            int idx = tid + t * 256;
            int row = idx >> 2;
            int kc  = (idx & 3) * 4;
            float4 v = *(const float4*)(Bblk + (size_t)row * K + k0 + kc);
            Bs[row * 18 + kc + 0] = v.x;
            Bs[row * 18 + kc + 1] = v.y;
            Bs[row * 18 + kc + 2] = v.z;
            Bs[row * 18 + kc + 3] = v.w;
        }
        __syncthreads();

        #pragma unroll
        for (int k = 0; k < 16; k++) {
            float a[8], b[8];
            *(float4*)&a[0] = *(const float4*)&As[k * 132 + ty * 8 + 0];
            *(float4*)&a[4] = *(const float4*)&As[k * 132 + ty * 8 + 4];
            #pragma unroll
            for (int j = 0; j < 8; j++) b[j] = Bs[(tx * 8 + j) * 18 + k];
            #pragma unroll
            for (int i = 0; i < 8; i++)
                #pragma unroll
                for (int j = 0; j < 8; j++)
                    acc[i][j] = fmaf(a[i], b[j], acc[i][j]);
        }
        __syncthreads();
    }

    #pragma unroll
    for (int i = 0; i < 8; i++) {
        int m = m0 + ty * 8 + i;
        #pragma unroll
        for (int j = 0; j < 8; j++) {
            int n = n0 + tx * 8 + j;
            if (HEAD) {
                float v = acc[i][j];
                if (n < NLOC)
                    C[(size_t)m * NLOC + n] = v + bias[n];
                else if (n < NHEAD)
                    C2[(size_t)m * NSC + (n - NLOC)] = v + bias2[n - NLOC];
            } else {
                float v = acc[i][j] + bias[n];
                if (RELU) v = fmaxf(v, 0.f);
                if (ROUND_OUT) v = tf32_rn(v);
                C[(size_t)m * GN + n] = v;
            }
        }
    }
#endif
}

// ---------------- launch ----------------
extern "C" void kernel_launch(void* const* d_in, const int* in_sizes, int n_in,
                              void* d_out, int out_size)
{
    const float* x      = (const float*)d_in[0];
    const float* rois   = (const float*)d_in[1];
    const float* W1     = (const float*)d_in[2];
    const float* b1     = (const float*)d_in[3];
    const float* W2     = (const float*)d_in[4];
    const float* b2     = (const float*)d_in[5];
    const float* W_loc  = (const float*)d_in[6];
    const float* b_loc  = (const float*)d_in[7];
    const float* W_sc   = (const float*)d_in[8];
    const float* b_sc   = (const float*)d_in[9];
    float* out = (float*)d_out;

    float *p_xt, *p_pool, *p_fc1, *p_fc2, *p_wt, *p_w1t, *p_w2t;
    cudaGetSymbolAddress((void**)&p_xt,   g_xt);
    cudaGetSymbolAddress((void**)&p_pool, g_pool);
    cudaGetSymbolAddress((void**)&p_fc1,  g_fc1);
    cudaGetSymbolAddress((void**)&p_fc2,  g_fc2);
    cudaGetSymbolAddress((void**)&p_wt,   g_wt);
    cudaGetSymbolAddress((void**)&p_w1t,  g_w1t);
    cudaGetSymbolAddress((void**)&p_w2t,  g_w2t);

    cudaFuncSetAttribute(gemm_kernel<true, true, false>,
                         cudaFuncAttributeMaxDynamicSharedMemorySize, SM_TOTAL);
    cudaFuncSetAttribute(gemm_kernel<false, false, true>,
                         cudaFuncAttributeMaxDynamicSharedMemorySize, SM_TOTAL);

    // 0) x -> xT[p][c]
    dim3 gx((HWP + 31) / 32, CCH / 32);
    xt_kernel<<<gx, 256>>>(x, p_xt);

    // 1) fused prep: pool + W1t(perm) + W2t + head weights
    prep_kernel<<<PREP_POOL + PREP_W1 + PREP_W2 + PREP_HEAD, 256>>>(
        p_xt, rois, p_pool, W1, p_w1t, W2, p_w2t, W_loc, W_sc, p_wt);

    // 2) fc1 = relu(pool @ W1 + b1)   K = 25088
    dim3 g(GN / 128, NROI / 128);
    gemm_kernel<true, true, false><<<g, 256, SM_TOTAL>>>(
        FCIN, p_pool, p_w1t, b1, nullptr, p_fc1, nullptr);

    // 3) fc2 = relu(fc1 @ W2 + b2)   K = 4096
    gemm_kernel<true, true, false><<<g, 256, SM_TOTAL>>>(
        FCD, p_fc1, p_w2t, b2, nullptr, p_fc2, nullptr);

    // 4) head GEMM: [512,4096] @ [128,4096]^T -> loc/score
    dim3 gh(1, NROI / 128);
    gemm_kernel<false, false, true><<<gh, 256, SM_TOTAL>>>(
        FCD, p_fc2, p_wt, b_loc, b_sc, out, out + (size_t)NROI * NLOC);
}